// round 6
// baseline (speedup 1.0000x reference)
#include <cuda_runtime.h>
#include <cuda_fp16.h>
#include <mma.h>
#include <cstdint>

using namespace nvcuda;

#define NNODES 50000
#define NEDGES 800000
#define LN_EPS 1e-5f

#define SCAN_BS 512
#define SCAN_NB ((NNODES + SCAN_BS - 1) / SCAN_BS)   // 98

// ---------------- scratch (static device globals; no runtime alloc) ----------
__device__ __align__(32) __half g_h16[NNODES * 128];    // GEMM output (fp16 messages)
__device__ __align__(32) __half g_feat16[NNODES * 128]; // LN output (fp16, next layer A)
__device__ __align__(32) __half g_w16_1[128 * 128];
__device__ __align__(32) __half g_w16_2[128 * 128];
__device__ __align__(32) __half g_w16_3[128 * 64];
__device__ float2 g_degcnt[NNODES];   // .x = weighted deg sum (atomic float), .y = count (atomic int)
__device__ float  g_dinv[NNODES];
__device__ int    g_off[NNODES + 1];
__device__ int    g_cur[NNODES];
__device__ int    g_bsum[SCAN_NB];
__device__ int    g_bpre[SCAN_NB];
__device__ int2   g_csr[NEDGES];      // {src, __float_as_int(dinv[src]*w)}

// ---------------- conversions -------------------------------------------------
__global__ void cvt_w_kernel(const float* __restrict__ W1, const float* __restrict__ W2,
                             const float* __restrict__ W3) {
    int i = blockIdx.x * blockDim.x + threadIdx.x;
    if (i < 16384) g_w16_1[i] = __float2half(W1[i]);
    else if (i < 32768) g_w16_2[i - 16384] = __float2half(W2[i - 16384]);
    else if (i < 40960) g_w16_3[i - 32768] = __float2half(W3[i - 32768]);
}

// ---------------- precompute ------------------------------------------------
// g_degcnt zeroed by cudaMemsetAsync before this; both atomics hit one 8B pair.
__global__ void count_kernel(const int* __restrict__ dst, const float* __restrict__ w) {
    int e = blockIdx.x * blockDim.x + threadIdx.x;
    if (e < NEDGES) {
        int d = dst[e];
        float2* p = &g_degcnt[d];
        atomicAdd(&p->x, w[e]);
        atomicAdd((int*)&p->y, 1);
    }
}

// phase 1: per-block exclusive scan of counts -> g_off (local), total -> g_bsum
__global__ void scan_block_kernel() {
    __shared__ int wsum[SCAN_BS / 32];
    int t = threadIdx.x;
    int lane = t & 31;
    int wid = t >> 5;
    int i = blockIdx.x * SCAN_BS + t;
    int v = (i < NNODES) ? __float_as_int(g_degcnt[i].y) : 0;

    int x = v;
#pragma unroll
    for (int o = 1; o < 32; o <<= 1) {
        int y = __shfl_up_sync(0xffffffffu, x, o);
        if (lane >= o) x += y;
    }
    if (lane == 31) wsum[wid] = x;
    __syncthreads();
    if (wid == 0) {
        int s = (lane < SCAN_BS / 32) ? wsum[lane] : 0;
#pragma unroll
        for (int o = 1; o < SCAN_BS / 32; o <<= 1) {
            int y = __shfl_up_sync(0xffffffffu, s, o);
            if (lane >= o) s += y;
        }
        if (lane < SCAN_BS / 32) wsum[lane] = s;
    }
    __syncthreads();
    int wpre = (wid == 0) ? 0 : wsum[wid - 1];
    int excl = wpre + x - v;
    if (i < NNODES) g_off[i] = excl;
    if (t == SCAN_BS - 1) g_bsum[blockIdx.x] = wpre + x;
}

// phase 2: ONE WARP scans the 98 block totals (4 per lane, shuffle scan)
__global__ void scan_tops_kernel() {
    int lane = threadIdx.x;
    int base = lane * 4;
    int v[4];
    int s = 0;
#pragma unroll
    for (int i = 0; i < 4; i++) {
        v[i] = (base + i < SCAN_NB) ? g_bsum[base + i] : 0;
        s += v[i];
    }
    int x = s;
#pragma unroll
    for (int o = 1; o < 32; o <<= 1) {
        int y = __shfl_up_sync(0xffffffffu, x, o);
        if (lane >= o) x += y;
    }
    int pre = x - s;   // exclusive prefix of this lane's chunk
#pragma unroll
    for (int i = 0; i < 4; i++) {
        if (base + i < SCAN_NB) g_bpre[base + i] = pre;
        pre += v[i];
    }
}

// phase 3: add block prefix, init cursors; fused dinv (deg includes +1 self-loop)
__global__ void scan_add_kernel() {
    int i = blockIdx.x * SCAN_BS + threadIdx.x;
    if (i < NNODES) {
        int off = g_off[i] + g_bpre[blockIdx.x];
        g_off[i] = off;
        g_cur[i] = off;
        g_dinv[i] = rsqrtf(g_degcnt[i].x + 1.0f);
    }
    if (i == 0) g_off[NNODES] = NEDGES;
}

// fill: store {src, dinv[src]*w}; dst-side dinv applied once in agg
__global__ void fill_kernel(const int* __restrict__ src, const int* __restrict__ dst,
                            const float* __restrict__ w) {
    int e = blockIdx.x * blockDim.x + threadIdx.x;
    if (e >= NEDGES) return;
    int s = src[e];
    int d = dst[e];
    float nm = g_dinv[s] * w[e];
    int pos = atomicAdd(&g_cur[d], 1);
    g_csr[pos] = make_int2(s, __float_as_int(nm));
}

// ---------------- tensor-core GEMM: H16 = fp16(A[N,128] @ W16[128,OUT]) ------
// A32: A is fp32 (layer 1, converted during tile load) else fp16.
template <int OUT, bool A32>
__global__ void gemm_wmma_kernel(const void* __restrict__ Av,
                                 const __half* __restrict__ W,
                                 __half* __restrict__ H) {
    constexpr int IN = 128;
    constexpr int ALD = IN + 16;
    constexpr int CLD = OUT + 8;
    constexpr int COLW = OUT / 2;
    constexpr int NF = COLW / 16;
    constexpr int ABYTES = 64 * ALD * 2;
    constexpr int CBYTES = 64 * CLD * 4;
    constexpr int BUFB = (ABYTES > CBYTES) ? ABYTES : CBYTES;

    __shared__ __align__(32) char buf[BUFB];
    __half (*As)[ALD] = (__half(*)[ALD])buf;
    float (*Cs)[CLD] = (float(*)[CLD])buf;

    const int t = threadIdx.x;
    const int row0 = blockIdx.x * 64;

    if (A32) {
        const float* A = (const float*)Av;
        // 64*128 floats; each iter: 4 floats -> half4 (8B) store
        for (int i = t; i < 64 * (IN / 4); i += 256) {
            int r = i >> 5;              // IN/4 = 32
            int kc = (i & 31) * 4;
            int gr = row0 + r;
            float4 v = make_float4(0.f, 0.f, 0.f, 0.f);
            if (gr < NNODES) v = *(const float4*)(A + (size_t)gr * IN + kc);
            __half2 a = __floats2half2_rn(v.x, v.y);
            __half2 b = __floats2half2_rn(v.z, v.w);
            uint2 u;
            u.x = *(uint32_t*)&a;
            u.y = *(uint32_t*)&b;
            *(uint2*)&As[r][kc] = u;
        }
    } else {
        const __half* A = (const __half*)Av;
        for (int i = t; i < 64 * (IN / 8); i += 256) {
            int r = i >> 4;              // IN/8 = 16
            int kc = (i & 15) * 8;
            int gr = row0 + r;
            uint4 v = make_uint4(0u, 0u, 0u, 0u);
            if (gr < NNODES) v = *(const uint4*)(A + (size_t)gr * IN + kc);
            *(uint4*)&As[r][kc] = v;
        }
    }
    __syncthreads();

    const int w = t >> 5;
    const int wr = w >> 1;
    const int wc = w & 1;

    wmma::fragment<wmma::accumulator, 16, 16, 16, float> cf[NF];
#pragma unroll
    for (int j = 0; j < NF; j++) wmma::fill_fragment(cf[j], 0.0f);

    wmma::fragment<wmma::matrix_a, 16, 16, 16, __half, wmma::row_major> af;
    wmma::fragment<wmma::matrix_b, 16, 16, 16, __half, wmma::row_major> bf;

#pragma unroll
    for (int k = 0; k < IN; k += 16) {
        wmma::load_matrix_sync(af, &As[wr * 16][k], ALD);
#pragma unroll
        for (int j = 0; j < NF; j++) {
            wmma::load_matrix_sync(bf, W + (size_t)k * OUT + wc * COLW + j * 16, OUT);
            wmma::mma_sync(cf[j], af, bf, cf[j]);
        }
    }

    __syncthreads();
#pragma unroll
    for (int j = 0; j < NF; j++)
        wmma::store_matrix_sync(&Cs[wr * 16][wc * COLW + j * 16], cf[j], CLD,
                                wmma::mem_row_major);
    __syncthreads();

    for (int i = t; i < 64 * (OUT / 2); i += 256) {
        int r = i / (OUT / 2);
        int c = (i % (OUT / 2)) * 2;
        int gr = row0 + r;
        if (gr < NNODES) {
            __half2 hv = __floats2half2_rn(Cs[r][c], Cs[r][c + 1]);
            *(__half2*)(H + (size_t)gr * OUT + c) = hv;
        }
    }
}

// ------- fused: gather-aggregate (CSR, fp16 msgs) + self + bias + LN ---------
__device__ __forceinline__ float4 ld_h16_row(const __half* H, int row, int lane) {
    uint2 u = *(const uint2*)(H + (size_t)row * 128 + lane * 4);
    float2 a = __half22float2(*(__half2*)&u.x);
    float2 b = __half22float2(*(__half2*)&u.y);
    return make_float4(a.x, a.y, b.x, b.y);
}
__device__ __forceinline__ float2 ld_h16_row64(const __half* H, int row, int lane) {
    uint32_t u = *(const uint32_t*)(H + (size_t)row * 64 + lane * 2);
    return __half22float2(*(__half2*)&u);
}

template <int DIM, bool RELU, bool HALF_OUT>
__global__ void agg_ln_kernel(const __half* __restrict__ H, const float* __restrict__ b,
                              const float* __restrict__ gm, const float* __restrict__ bt,
                              void* __restrict__ Ov) {
    int gt = blockIdx.x * blockDim.x + threadIdx.x;
    int node = gt >> 5;
    if (node >= NNODES) return;
    int lane = gt & 31;

    float di = g_dinv[node];
    float d2 = di * di;
    int beg = g_off[node];
    int end = g_off[node + 1];

    if (DIM == 128) {
        int c = lane * 4;
        float4 ae = make_float4(0.f, 0.f, 0.f, 0.f);   // edge sum (pre dinv[d])

        int j = beg;
        for (; j + 3 < end; j += 4) {
            int2 e0 = __ldg(&g_csr[j]);
            int2 e1 = __ldg(&g_csr[j + 1]);
            int2 e2 = __ldg(&g_csr[j + 2]);
            int2 e3 = __ldg(&g_csr[j + 3]);
            float4 v0 = ld_h16_row(H, e0.x, lane);
            float4 v1 = ld_h16_row(H, e1.x, lane);
            float4 v2 = ld_h16_row(H, e2.x, lane);
            float4 v3 = ld_h16_row(H, e3.x, lane);
            float n0 = __int_as_float(e0.y);
            float n1 = __int_as_float(e1.y);
            float n2 = __int_as_float(e2.y);
            float n3 = __int_as_float(e3.y);
            ae.x += n0 * v0.x + n1 * v1.x + n2 * v2.x + n3 * v3.x;
            ae.y += n0 * v0.y + n1 * v1.y + n2 * v2.y + n3 * v3.y;
            ae.z += n0 * v0.z + n1 * v1.z + n2 * v2.z + n3 * v3.z;
            ae.w += n0 * v0.w + n1 * v1.w + n2 * v2.w + n3 * v3.w;
        }
        for (; j < end; j++) {
            int2 e = __ldg(&g_csr[j]);
            float4 v = ld_h16_row(H, e.x, lane);
            float nm = __int_as_float(e.y);
            ae.x += nm * v.x;
            ae.y += nm * v.y;
            ae.z += nm * v.z;
            ae.w += nm * v.w;
        }

        float4 hv = ld_h16_row(H, node, lane);
        float4 bv = *(const float4*)(b + c);
        float4 acc;
        acc.x = d2 * hv.x + bv.x + di * ae.x;
        acc.y = d2 * hv.y + bv.y + di * ae.y;
        acc.z = d2 * hv.z + bv.z + di * ae.z;
        acc.w = d2 * hv.w + bv.w + di * ae.w;

        float s1 = acc.x + acc.y + acc.z + acc.w;
        float s2 = acc.x * acc.x + acc.y * acc.y + acc.z * acc.z + acc.w * acc.w;
#pragma unroll
        for (int o = 16; o > 0; o >>= 1) {
            s1 += __shfl_xor_sync(0xffffffffu, s1, o);
            s2 += __shfl_xor_sync(0xffffffffu, s2, o);
        }
        float mean = s1 * (1.0f / 128.0f);
        float var = s2 * (1.0f / 128.0f) - mean * mean;
        float inv = rsqrtf(var + LN_EPS);
        float4 gv = *(const float4*)(gm + c);
        float4 tv = *(const float4*)(bt + c);
        float4 o4;
        o4.x = (acc.x - mean) * inv * gv.x + tv.x;
        o4.y = (acc.y - mean) * inv * gv.y + tv.y;
        o4.z = (acc.z - mean) * inv * gv.z + tv.z;
        o4.w = (acc.w - mean) * inv * gv.w + tv.w;
        if (RELU) {
            o4.x = fmaxf(o4.x, 0.0f);
            o4.y = fmaxf(o4.y, 0.0f);
            o4.z = fmaxf(o4.z, 0.0f);
            o4.w = fmaxf(o4.w, 0.0f);
        }
        if (HALF_OUT) {
            __half* O = (__half*)Ov;
            __half2 ha = __floats2half2_rn(o4.x, o4.y);
            __half2 hb = __floats2half2_rn(o4.z, o4.w);
            uint2 u;
            u.x = *(uint32_t*)&ha;
            u.y = *(uint32_t*)&hb;
            *(uint2*)(O + (size_t)node * 128 + c) = u;
        } else {
            float* O = (float*)Ov;
            *(float4*)(O + (size_t)node * 128 + c) = o4;
        }
    } else {   // DIM == 64
        int c = lane * 2;
        float2 ae = make_float2(0.f, 0.f);

        int j = beg;
        for (; j + 3 < end; j += 4) {
            int2 e0 = __ldg(&g_csr[j]);
            int2 e1 = __ldg(&g_csr[j + 1]);
            int2 e2 = __ldg(&g_csr[j + 2]);
            int2 e3 = __ldg(&g_csr[j + 3]);
            float2 v0 = ld_h16_row64(H, e0.x, lane);
            float2 v1 = ld_h16_row64(H, e1.x, lane);
            float2 v2 = ld_h16_row64(H, e2.x, lane);
            float2 v3 = ld_h16_row64(H, e3.x, lane);
            float n0 = __int_as_float(e0.y);
            float n1 = __int_as_float(e1.y);
            float n2 = __int_as_float(e2.y);
            float n3 = __int_as_float(e3.y);
            ae.x += n0 * v0.x + n1 * v1.x + n2 * v2.x + n3 * v3.x;
            ae.y += n0 * v0.y + n1 * v1.y + n2 * v2.y + n3 * v3.y;
        }
        for (; j < end; j++) {
            int2 e = __ldg(&g_csr[j]);
            float2 v = ld_h16_row64(H, e.x, lane);
            float nm = __int_as_float(e.y);
            ae.x += nm * v.x;
            ae.y += nm * v.y;
        }

        float2 hv = ld_h16_row64(H, node, lane);
        float2 bv = *(const float2*)(b + c);
        float2 acc;
        acc.x = d2 * hv.x + bv.x + di * ae.x;
        acc.y = d2 * hv.y + bv.y + di * ae.y;

        float s1 = acc.x + acc.y;
        float s2 = acc.x * acc.x + acc.y * acc.y;
#pragma unroll
        for (int o = 16; o > 0; o >>= 1) {
            s1 += __shfl_xor_sync(0xffffffffu, s1, o);
            s2 += __shfl_xor_sync(0xffffffffu, s2, o);
        }
        float mean = s1 * (1.0f / 64.0f);
        float var = s2 * (1.0f / 64.0f) - mean * mean;
        float inv = rsqrtf(var + LN_EPS);
        float2 gv = *(const float2*)(gm + c);
        float2 tv = *(const float2*)(bt + c);
        float2 o2;
        o2.x = (acc.x - mean) * inv * gv.x + tv.x;
        o2.y = (acc.y - mean) * inv * gv.y + tv.y;
        if (RELU) {
            o2.x = fmaxf(o2.x, 0.0f);
            o2.y = fmaxf(o2.y, 0.0f);
        }
        float* O = (float*)Ov;
        *(float2*)(O + (size_t)node * 64 + c) = o2;
    }
}

// ---------------- host launch -------------------------------------------------
extern "C" void kernel_launch(void* const* d_in, const int* in_sizes, int n_in,
                              void* d_out, int out_size) {
    const float* x  = (const float*)d_in[0];
    const int*   ei = (const int*)d_in[1];
    const float* ew = (const float*)d_in[2];
    const float* W1 = (const float*)d_in[3];
    const float* b1 = (const float*)d_in[4];
    const float* g1 = (const float*)d_in[5];
    const float* t1 = (const float*)d_in[6];
    const float* W2 = (const float*)d_in[7];
    const float* b2 = (const float*)d_in[8];
    const float* g2 = (const float*)d_in[9];
    const float* t2 = (const float*)d_in[10];
    const float* W3 = (const float*)d_in[11];
    const float* b3 = (const float*)d_in[12];
    const float* g3 = (const float*)d_in[13];
    const float* t3 = (const float*)d_in[14];
    const int* src = ei;
    const int* dst = ei + NEDGES;

    __half *h16, *feat16, *w16_1, *w16_2, *w16_3;
    float2* degcnt;
    cudaGetSymbolAddress((void**)&h16, g_h16);
    cudaGetSymbolAddress((void**)&feat16, g_feat16);
    cudaGetSymbolAddress((void**)&w16_1, g_w16_1);
    cudaGetSymbolAddress((void**)&w16_2, g_w16_2);
    cudaGetSymbolAddress((void**)&w16_3, g_w16_3);
    cudaGetSymbolAddress((void**)&degcnt, g_degcnt);

    const int TB = 256;
    const int nblk_E = (NEDGES + TB - 1) / TB;
    const int nblk_row = (NNODES * 32 + TB - 1) / TB;    // warp per node
    const int nblk_gemm = (NNODES + 63) / 64;

    // precompute
    cudaMemsetAsync(degcnt, 0, NNODES * sizeof(float2));
    cvt_w_kernel<<<(40960 + TB - 1) / TB, TB>>>(W1, W2, W3);
    count_kernel<<<nblk_E, TB>>>(dst, ew);
    scan_block_kernel<<<SCAN_NB, SCAN_BS>>>();
    scan_tops_kernel<<<1, 32>>>();
    scan_add_kernel<<<SCAN_NB, SCAN_BS>>>();
    fill_kernel<<<nblk_E, TB>>>(src, dst, ew);

    // layer 1 (fp32 A, converted in tile load)
    gemm_wmma_kernel<128, true><<<nblk_gemm, 256>>>(x, w16_1, h16);
    agg_ln_kernel<128, true, true><<<nblk_row, TB>>>(h16, b1, g1, t1, feat16);

    // layer 2
    gemm_wmma_kernel<128, false><<<nblk_gemm, 256>>>(feat16, w16_2, h16);
    agg_ln_kernel<128, true, true><<<nblk_row, TB>>>(h16, b2, g2, t2, feat16);

    // layer 3 (dout = 64, no relu), fp32 output straight to d_out
    gemm_wmma_kernel<64, false><<<nblk_gemm, 256>>>(feat16, w16_3, h16);
    agg_ln_kernel<64, false, false><<<nblk_row, TB>>>(h16, b3, g3, t3, d_out);
}

// round 7
// speedup vs baseline: 1.5182x; 1.5182x over previous
#include <cuda_runtime.h>
#include <cuda_fp16.h>
#include <mma.h>
#include <cstdint>

using namespace nvcuda;

#define NNODES 50000
#define NEDGES 800000
#define LN_EPS 1e-5f

#define SCAN_BS 512
#define SCAN_NB ((NNODES + SCAN_BS - 1) / SCAN_BS)   // 98
#define TB 256
#define GEMM_NB ((NNODES + 63) / 64)                 // 782
#define EDGE_NB ((NEDGES + TB - 1) / TB)             // 3125

// ---------------- scratch (static device globals; no runtime alloc) ----------
__device__ __align__(32) __half g_h16[NNODES * 128];    // GEMM output (fp16 messages)
__device__ __align__(32) __half g_feat16[NNODES * 128]; // LN output (fp16, next layer A)
__device__ __align__(32) __half g_w16_1[128 * 128];
__device__ __align__(32) __half g_w16_2[128 * 128];
__device__ __align__(32) __half g_w16_3[128 * 64];
__device__ float  g_deg[NNODES];      // weighted in-degree (memset 0; +1 self-loop at dinv)
__device__ float  g_dinv[NNODES];
__device__ int    g_cnt[NNODES];
__device__ int    g_off[NNODES + 1];
__device__ int    g_cur[NNODES];
__device__ int    g_bsum[SCAN_NB];
__device__ int    g_bpre[SCAN_NB];
__device__ int    g_csr_src[NEDGES];
__device__ float  g_csr_nrm[NEDGES];

// ---------------- conversions -------------------------------------------------
__global__ void cvt_w_kernel(const float* __restrict__ W1, const float* __restrict__ W2,
                             const float* __restrict__ W3) {
    int i = blockIdx.x * blockDim.x + threadIdx.x;
    if (i < 16384) g_w16_1[i] = __float2half(W1[i]);
    else if (i < 32768) g_w16_2[i - 16384] = __float2half(W2[i - 16384]);
    else if (i < 40960) g_w16_3[i - 32768] = __float2half(W3[i - 32768]);
}

// ---------------- precompute bodies ------------------------------------------
__device__ __forceinline__ void count_body(const int* __restrict__ dst,
                                           const float* __restrict__ w, int blk) {
    int e = blk * TB + threadIdx.x;
    if (e < NEDGES) {
        int d = dst[e];
        atomicAdd(&g_deg[d], w[e]);    // separate arrays: atomics spread over
        atomicAdd(&g_cnt[d], 1);       // independent lines/LTS partitions
    }
}

// ---------------- tensor-core GEMM body --------------------------------------
// H16 = fp16(A[N,128] @ W16[128,OUT]); A32: A fp32 (converted in tile load).
template <int OUT, bool A32>
__device__ __forceinline__ void gemm_body(const void* __restrict__ Av,
                                          const __half* __restrict__ W,
                                          __half* __restrict__ H, int blk) {
    constexpr int IN = 128;
    constexpr int ALD = IN + 16;
    constexpr int CLD = OUT + 8;
    constexpr int COLW = OUT / 2;
    constexpr int NF = COLW / 16;
    constexpr int ABYTES = 64 * ALD * 2;
    constexpr int CBYTES = 64 * CLD * 4;
    constexpr int BUFB = (ABYTES > CBYTES) ? ABYTES : CBYTES;

    __shared__ __align__(32) char buf[BUFB];
    __half (*As)[ALD] = (__half(*)[ALD])buf;
    float (*Cs)[CLD] = (float(*)[CLD])buf;

    const int t = threadIdx.x;
    const int row0 = blk * 64;

    if (A32) {
        const float* A = (const float*)Av;
        for (int i = t; i < 64 * (IN / 4); i += 256) {
            int r = i >> 5;
            int kc = (i & 31) * 4;
            int gr = row0 + r;
            float4 v = make_float4(0.f, 0.f, 0.f, 0.f);
            if (gr < NNODES) v = *(const float4*)(A + (size_t)gr * IN + kc);
            __half2 a = __floats2half2_rn(v.x, v.y);
            __half2 b = __floats2half2_rn(v.z, v.w);
            uint2 u;
            u.x = *(uint32_t*)&a;
            u.y = *(uint32_t*)&b;
            *(uint2*)&As[r][kc] = u;
        }
    } else {
        const __half* A = (const __half*)Av;
        for (int i = t; i < 64 * (IN / 8); i += 256) {
            int r = i >> 4;
            int kc = (i & 15) * 8;
            int gr = row0 + r;
            uint4 v = make_uint4(0u, 0u, 0u, 0u);
            if (gr < NNODES) v = *(const uint4*)(A + (size_t)gr * IN + kc);
            *(uint4*)&As[r][kc] = v;
        }
    }
    __syncthreads();

    const int w = t >> 5;
    const int wr = w >> 1;
    const int wc = w & 1;

    wmma::fragment<wmma::accumulator, 16, 16, 16, float> cf[NF];
#pragma unroll
    for (int j = 0; j < NF; j++) wmma::fill_fragment(cf[j], 0.0f);

    wmma::fragment<wmma::matrix_a, 16, 16, 16, __half, wmma::row_major> af;
    wmma::fragment<wmma::matrix_b, 16, 16, 16, __half, wmma::row_major> bf;

#pragma unroll
    for (int k = 0; k < IN; k += 16) {
        wmma::load_matrix_sync(af, &As[wr * 16][k], ALD);
#pragma unroll
        for (int j = 0; j < NF; j++) {
            wmma::load_matrix_sync(bf, W + (size_t)k * OUT + wc * COLW + j * 16, OUT);
            wmma::mma_sync(cf[j], af, bf, cf[j]);
        }
    }

    __syncthreads();
#pragma unroll
    for (int j = 0; j < NF; j++)
        wmma::store_matrix_sync(&Cs[wr * 16][wc * COLW + j * 16], cf[j], CLD,
                                wmma::mem_row_major);
    __syncthreads();

    for (int i = t; i < 64 * (OUT / 2); i += 256) {
        int r = i / (OUT / 2);
        int c = (i % (OUT / 2)) * 2;
        int gr = row0 + r;
        if (gr < NNODES) {
            __half2 hv = __floats2half2_rn(Cs[r][c], Cs[r][c + 1]);
            *(__half2*)(H + (size_t)gr * OUT + c) = hv;
        }
    }
}

// fused: gemm1 (blocks [0,GEMM_NB)) + count (blocks [GEMM_NB, GEMM_NB+EDGE_NB))
__global__ void __launch_bounds__(256) fused_gemm1_count_kernel(
    const float* __restrict__ x, const int* __restrict__ dst,
    const float* __restrict__ ew) {
    if (blockIdx.x < GEMM_NB) {
        gemm_body<128, true>(x, g_w16_1, g_h16, blockIdx.x);
    } else {
        count_body(dst, ew, blockIdx.x - GEMM_NB);
    }
}

template <int OUT>
__global__ void __launch_bounds__(256) gemm_kernel(const __half* __restrict__ A,
                                                   const __half* __restrict__ W,
                                                   __half* __restrict__ H) {
    gemm_body<OUT, false>(A, W, H, blockIdx.x);
}

// ---------------- scan --------------------------------------------------------
__global__ void scan_block_kernel() {
    __shared__ int wsum[SCAN_BS / 32];
    int t = threadIdx.x;
    int lane = t & 31;
    int wid = t >> 5;
    int i = blockIdx.x * SCAN_BS + t;
    int v = (i < NNODES) ? g_cnt[i] : 0;

    int x = v;
#pragma unroll
    for (int o = 1; o < 32; o <<= 1) {
        int y = __shfl_up_sync(0xffffffffu, x, o);
        if (lane >= o) x += y;
    }
    if (lane == 31) wsum[wid] = x;
    __syncthreads();
    if (wid == 0) {
        int s = (lane < SCAN_BS / 32) ? wsum[lane] : 0;
#pragma unroll
        for (int o = 1; o < SCAN_BS / 32; o <<= 1) {
            int y = __shfl_up_sync(0xffffffffu, s, o);
            if (lane >= o) s += y;
        }
        if (lane < SCAN_BS / 32) wsum[lane] = s;
    }
    __syncthreads();
    int wpre = (wid == 0) ? 0 : wsum[wid - 1];
    int excl = wpre + x - v;
    if (i < NNODES) g_off[i] = excl;
    if (t == SCAN_BS - 1) g_bsum[blockIdx.x] = wpre + x;
}

// one warp scans the 98 block totals
__global__ void scan_tops_kernel() {
    int lane = threadIdx.x;
    int base = lane * 4;
    int v[4];
    int s = 0;
#pragma unroll
    for (int i = 0; i < 4; i++) {
        v[i] = (base + i < SCAN_NB) ? g_bsum[base + i] : 0;
        s += v[i];
    }
    int x = s;
#pragma unroll
    for (int o = 1; o < 32; o <<= 1) {
        int y = __shfl_up_sync(0xffffffffu, x, o);
        if (lane >= o) x += y;
    }
    int pre = x - s;
#pragma unroll
    for (int i = 0; i < 4; i++) {
        if (base + i < SCAN_NB) g_bpre[base + i] = pre;
        pre += v[i];
    }
}

__global__ void scan_add_kernel() {
    int i = blockIdx.x * SCAN_BS + threadIdx.x;
    if (i < NNODES) {
        int off = g_off[i] + g_bpre[blockIdx.x];
        g_off[i] = off;
        g_cur[i] = off;
        g_dinv[i] = rsqrtf(g_deg[i] + 1.0f);   // +1 = self-loop weight
    }
    if (i == 0) g_off[NNODES] = NEDGES;
}

__global__ void fill_kernel(const int* __restrict__ src, const int* __restrict__ dst,
                            const float* __restrict__ w) {
    int e = blockIdx.x * blockDim.x + threadIdx.x;
    if (e >= NEDGES) return;
    int s = src[e];
    int d = dst[e];
    float nm = g_dinv[s] * w[e] * g_dinv[d];
    int pos = atomicAdd(&g_cur[d], 1);
    g_csr_src[pos] = s;
    g_csr_nrm[pos] = nm;
}

// ------- fused: gather-aggregate (CSR, fp16 msgs) + self + bias + LN ---------
__device__ __forceinline__ float4 ld_h16_row(const __half* H, int row, int lane) {
    uint2 u = *(const uint2*)(H + (size_t)row * 128 + lane * 4);
    float2 a = __half22float2(*(__half2*)&u.x);
    float2 b = __half22float2(*(__half2*)&u.y);
    return make_float4(a.x, a.y, b.x, b.y);
}
__device__ __forceinline__ float2 ld_h16_row64(const __half* H, int row, int lane) {
    uint32_t u = *(const uint32_t*)(H + (size_t)row * 64 + lane * 2);
    return __half22float2(*(__half2*)&u);
}

template <int DIM, bool RELU, bool HALF_OUT>
__global__ void agg_ln_kernel(const __half* __restrict__ H, const float* __restrict__ b,
                              const float* __restrict__ gm, const float* __restrict__ bt,
                              void* __restrict__ Ov) {
    int gt = blockIdx.x * blockDim.x + threadIdx.x;
    int node = gt >> 5;
    if (node >= NNODES) return;
    int lane = gt & 31;

    float di = g_dinv[node];
    float d2 = di * di;
    int beg = g_off[node];
    int end = g_off[node + 1];

    if (DIM == 128) {
        int c = lane * 4;
        float4 hv = ld_h16_row(H, node, lane);
        float4 bv = *(const float4*)(b + c);
        float4 acc;
        acc.x = d2 * hv.x + bv.x;
        acc.y = d2 * hv.y + bv.y;
        acc.z = d2 * hv.z + bv.z;
        acc.w = d2 * hv.w + bv.w;

        int j = beg;
        for (; j + 3 < end; j += 4) {
            int s0 = __ldg(&g_csr_src[j]);
            int s1 = __ldg(&g_csr_src[j + 1]);
            int s2 = __ldg(&g_csr_src[j + 2]);
            int s3 = __ldg(&g_csr_src[j + 3]);
            float n0 = __ldg(&g_csr_nrm[j]);
            float n1 = __ldg(&g_csr_nrm[j + 1]);
            float n2 = __ldg(&g_csr_nrm[j + 2]);
            float n3 = __ldg(&g_csr_nrm[j + 3]);
            float4 v0 = ld_h16_row(H, s0, lane);
            float4 v1 = ld_h16_row(H, s1, lane);
            float4 v2 = ld_h16_row(H, s2, lane);
            float4 v3 = ld_h16_row(H, s3, lane);
            acc.x += n0 * v0.x + n1 * v1.x + n2 * v2.x + n3 * v3.x;
            acc.y += n0 * v0.y + n1 * v1.y + n2 * v2.y + n3 * v3.y;
            acc.z += n0 * v0.z + n1 * v1.z + n2 * v2.z + n3 * v3.z;
            acc.w += n0 * v0.w + n1 * v1.w + n2 * v2.w + n3 * v3.w;
        }
        for (; j < end; j++) {
            int s = __ldg(&g_csr_src[j]);
            float nm = __ldg(&g_csr_nrm[j]);
            float4 v = ld_h16_row(H, s, lane);
            acc.x += nm * v.x;
            acc.y += nm * v.y;
            acc.z += nm * v.z;
            acc.w += nm * v.w;
        }

        float s1 = acc.x + acc.y + acc.z + acc.w;
        float s2 = acc.x * acc.x + acc.y * acc.y + acc.z * acc.z + acc.w * acc.w;
#pragma unroll
        for (int o = 16; o > 0; o >>= 1) {
            s1 += __shfl_xor_sync(0xffffffffu, s1, o);
            s2 += __shfl_xor_sync(0xffffffffu, s2, o);
        }
        float mean = s1 * (1.0f / 128.0f);
        float var = s2 * (1.0f / 128.0f) - mean * mean;
        float inv = rsqrtf(var + LN_EPS);
        float4 gv = *(const float4*)(gm + c);
        float4 tv = *(const float4*)(bt + c);
        float4 o4;
        o4.x = (acc.x - mean) * inv * gv.x + tv.x;
        o4.y = (acc.y - mean) * inv * gv.y + tv.y;
        o4.z = (acc.z - mean) * inv * gv.z + tv.z;
        o4.w = (acc.w - mean) * inv * gv.w + tv.w;
        if (RELU) {
            o4.x = fmaxf(o4.x, 0.0f);
            o4.y = fmaxf(o4.y, 0.0f);
            o4.z = fmaxf(o4.z, 0.0f);
            o4.w = fmaxf(o4.w, 0.0f);
        }
        if (HALF_OUT) {
            __half* O = (__half*)Ov;
            __half2 ha = __floats2half2_rn(o4.x, o4.y);
            __half2 hb = __floats2half2_rn(o4.z, o4.w);
            uint2 u;
            u.x = *(uint32_t*)&ha;
            u.y = *(uint32_t*)&hb;
            *(uint2*)(O + (size_t)node * 128 + c) = u;
        } else {
            float* O = (float*)Ov;
            *(float4*)(O + (size_t)node * 128 + c) = o4;
        }
    } else {   // DIM == 64
        int c = lane * 2;
        float2 hv = ld_h16_row64(H, node, lane);
        float2 bv = *(const float2*)(b + c);
        float2 acc;
        acc.x = d2 * hv.x + bv.x;
        acc.y = d2 * hv.y + bv.y;

        int j = beg;
        for (; j + 3 < end; j += 4) {
            int s0 = __ldg(&g_csr_src[j]);
            int s1 = __ldg(&g_csr_src[j + 1]);
            int s2 = __ldg(&g_csr_src[j + 2]);
            int s3 = __ldg(&g_csr_src[j + 3]);
            float n0 = __ldg(&g_csr_nrm[j]);
            float n1 = __ldg(&g_csr_nrm[j + 1]);
            float n2 = __ldg(&g_csr_nrm[j + 2]);
            float n3 = __ldg(&g_csr_nrm[j + 3]);
            float2 v0 = ld_h16_row64(H, s0, lane);
            float2 v1 = ld_h16_row64(H, s1, lane);
            float2 v2 = ld_h16_row64(H, s2, lane);
            float2 v3 = ld_h16_row64(H, s3, lane);
            acc.x += n0 * v0.x + n1 * v1.x + n2 * v2.x + n3 * v3.x;
            acc.y += n0 * v0.y + n1 * v1.y + n2 * v2.y + n3 * v3.y;
        }
        for (; j < end; j++) {
            int s = __ldg(&g_csr_src[j]);
            float nm = __ldg(&g_csr_nrm[j]);
            float2 v = ld_h16_row64(H, s, lane);
            acc.x += nm * v.x;
            acc.y += nm * v.y;
        }

        float s1 = acc.x + acc.y;
        float s2 = acc.x * acc.x + acc.y * acc.y;
#pragma unroll
        for (int o = 16; o > 0; o >>= 1) {
            s1 += __shfl_xor_sync(0xffffffffu, s1, o);
            s2 += __shfl_xor_sync(0xffffffffu, s2, o);
        }
        float mean = s1 * (1.0f / 64.0f);
        float var = s2 * (1.0f / 64.0f) - mean * mean;
        float inv = rsqrtf(var + LN_EPS);
        float2 gv = *(const float2*)(gm + c);
        float2 tv = *(const float2*)(bt + c);
        float2 o2;
        o2.x = (acc.x - mean) * inv * gv.x + tv.x;
        o2.y = (acc.y - mean) * inv * gv.y + tv.y;
        if (RELU) {
            o2.x = fmaxf(o2.x, 0.0f);
            o2.y = fmaxf(o2.y, 0.0f);
        }
        float* O = (float*)Ov;
        *(float2*)(O + (size_t)node * 64 + c) = o2;
    }
}

// ---------------- host launch -------------------------------------------------
extern "C" void kernel_launch(void* const* d_in, const int* in_sizes, int n_in,
                              void* d_out, int out_size) {
    const float* x  = (const float*)d_in[0];
    const int*   ei = (const int*)d_in[1];
    const float* ew = (const float*)d_in[2];
    const float* W1 = (const float*)d_in[3];
    const float* b1 = (const float*)d_in[4];
    const float* g1 = (const float*)d_in[5];
    const float* t1 = (const float*)d_in[6];
    const float* W2 = (const float*)d_in[7];
    const float* b2 = (const float*)d_in[8];
    const float* g2 = (const float*)d_in[9];
    const float* t2 = (const float*)d_in[10];
    const float* W3 = (const float*)d_in[11];
    const float* b3 = (const float*)d_in[12];
    const float* g3 = (const float*)d_in[13];
    const float* t3 = (const float*)d_in[14];
    const int* src = ei;
    const int* dst = ei + NEDGES;

    __half *h16, *feat16, *w16_2, *w16_3;
    float *deg;
    int *cnt;
    cudaGetSymbolAddress((void**)&h16, g_h16);
    cudaGetSymbolAddress((void**)&feat16, g_feat16);
    cudaGetSymbolAddress((void**)&w16_2, g_w16_2);
    cudaGetSymbolAddress((void**)&w16_3, g_w16_3);
    cudaGetSymbolAddress((void**)&deg, g_deg);
    cudaGetSymbolAddress((void**)&cnt, g_cnt);

    const int nblk_row = (NNODES * 32 + TB - 1) / TB;    // warp per node

    // precompute
    cudaMemsetAsync(deg, 0, NNODES * sizeof(float));
    cudaMemsetAsync(cnt, 0, NNODES * sizeof(int));
    cvt_w_kernel<<<(40960 + TB - 1) / TB, TB>>>(W1, W2, W3);
    // overlapped: layer-1 GEMM (independent) + edge counting
    fused_gemm1_count_kernel<<<GEMM_NB + EDGE_NB, TB>>>(x, dst, ew);
    scan_block_kernel<<<SCAN_NB, SCAN_BS>>>();
    scan_tops_kernel<<<1, 32>>>();
    scan_add_kernel<<<SCAN_NB, SCAN_BS>>>();
    fill_kernel<<<EDGE_NB, TB>>>(src, dst, ew);

    // layer 1 aggregation (gemm1 already done in fused kernel)
    agg_ln_kernel<128, true, true><<<nblk_row, TB>>>(h16, b1, g1, t1, feat16);

    // layer 2
    gemm_kernel<128><<<GEMM_NB, TB>>>(feat16, w16_2, h16);
    agg_ln_kernel<128, true, true><<<nblk_row, TB>>>(h16, b2, g2, t2, feat16);

    // layer 3 (dout = 64, no relu), fp32 output straight to d_out
    gemm_kernel<64><<<GEMM_NB, TB>>>(feat16, w16_3, h16);
    agg_ln_kernel<64, false, false><<<nblk_row, TB>>>(h16, b3, g3, t3, d_out);
}